// round 8
// baseline (speedup 1.0000x reference)
#include <cuda_runtime.h>
#include <cuda_bf16.h>
#include <cstdint>

// ResiduePooling: scatter_mean(atom_features[2e6,128], residue_index(sorted) -> [250000,128])
//
// SINGLE fused kernel, R4 streaming structure preserved:
//   one warp per residue r. Segment bounds found per-warp via interpolated
//   32-ary lower_bound on the sorted (L2-resident) index:
//     guess g = r*n/R, window +-6144 (>8 sigma of the binomial deviation;
//     full-range fallback for safety), two ballot-narrowing rounds, one
//     coalesced final scan; segment end via coalesced forward scan.
//   Then: lane owns one float4 of the 128-wide row; 512B coalesced LDG.128
//   streams (evict-streaming), scale by 1/count, one 512B row store.
//   Empty residues (s==e) write zeros. Atomic-free, deterministic, 1 launch.

#define NUM_RESIDUES 250000
#define FEAT_DIM 128
#define WINDOW 6144

__device__ __forceinline__ bool detect_is64(const int* __restrict__ v, int n) {
    // int64 little-endian values < 2^31: every odd int32 slot is zero.
    int p0 = __ldg(v + 1);
    int p1 = __ldg(v + ((n > 1002) ? 1001 : 1));
    int p2 = __ldg(v + ((n > 100002) ? 100001 : 1));
    int p3 = __ldg(v + (n - 1));
    return ((p0 | p1 | p2 | p3) == 0);
}

__device__ __forceinline__ int idx_at(const long long* __restrict__ p64,
                                      const int* __restrict__ p32,
                                      bool is64, int j) {
    return is64 ? (int)__ldg(p64 + j) : __ldg(p32 + j);
}

__global__ void __launch_bounds__(64) fused_pool_kernel(const float* __restrict__ feat,
                                                        const void* __restrict__ idxv,
                                                        int n,
                                                        float* __restrict__ out) {
    const int r    = (blockIdx.x * blockDim.x + threadIdx.x) >> 5;  // residue id
    const int lane = threadIdx.x & 31;
    if (r >= NUM_RESIDUES) return;

    const bool is64 = detect_is64((const int*)idxv, n);
    const long long* __restrict__ p64 = (const long long*)idxv;
    const int* __restrict__       p32 = (const int*)idxv;

    // ---- lower_bound(r): find s = min{i : idx[i] >= r} ----
    int g  = (int)(((long long)r * (long long)n) / NUM_RESIDUES);
    int lo = g - WINDOW; if (lo < 0) lo = 0;
    int hi = g + WINDOW; if (hi > n) hi = n;

    // Verify the window brackets the boundary (lane 0 probes, broadcast).
    int okflag = 1;
    if (lane == 0) {
        bool okL = (lo == 0) || (idx_at(p64, p32, is64, lo - 1) < r);
        bool okH = (hi == n) || (idx_at(p64, p32, is64, hi) >= r);
        okflag = (okL && okH) ? 1 : 0;
    }
    okflag = __shfl_sync(0xffffffffu, okflag, 0);
    if (!okflag) { lo = 0; hi = n; }   // ~never taken

    // 32-ary narrowing: invariant lo <= s <= hi.
    while (hi - lo > 32) {
        long long span = hi - lo;
        int pos = lo + (int)((span * lane) >> 5);
        int v = idx_at(p64, p32, is64, pos);
        unsigned bal = __ballot_sync(0xffffffffu, v >= r);
        if (bal == 0) {
            lo = lo + (int)((span * 31) >> 5) + 1;
        } else {
            int f = __ffs(bal) - 1;
            int posf = lo + (int)((span * f) >> 5);
            if (f > 0) lo = lo + (int)((span * (f - 1)) >> 5) + 1;
            hi = posf;
        }
    }
    int s;
    {
        int j = lo + lane;
        int v = (j < n) ? idx_at(p64, p32, is64, j) : 0x7fffffff;
        unsigned bal = __ballot_sync(0xffffffffu, v >= r);
        s = bal ? (lo + __ffs(bal) - 1) : hi;
    }

    // ---- segment end e = min{i >= s : idx[i] >= r+1} (coalesced scan) ----
    int e = n;
    for (int off = s; off < n; off += 32) {
        int j = off + lane;
        int v = (j < n) ? idx_at(p64, p32, is64, j) : 0x7fffffff;
        unsigned bal = __ballot_sync(0xffffffffu, v >= r + 1);
        if (bal) { e = off + __ffs(bal) - 1; break; }
    }

    const int cnt = e - s;   // 0 for empty residues (idx[s] > r)

    // ---- stream-pool [s, e): identical to the proven R4 loop ----
    const float4* __restrict__ p = (const float4*)(feat + (size_t)s * FEAT_DIM) + lane;

    float4 acc0 = make_float4(0.f, 0.f, 0.f, 0.f);
    float4 acc1 = make_float4(0.f, 0.f, 0.f, 0.f);

    int a = 0;
    for (; a + 4 <= cnt; a += 4) {
        float4 v0 = __ldcs(p);
        float4 v1 = __ldcs(p + 32);
        float4 v2 = __ldcs(p + 64);
        float4 v3 = __ldcs(p + 96);
        p += 128;
        acc0.x += v0.x; acc0.y += v0.y; acc0.z += v0.z; acc0.w += v0.w;
        acc1.x += v1.x; acc1.y += v1.y; acc1.z += v1.z; acc1.w += v1.w;
        acc0.x += v2.x; acc0.y += v2.y; acc0.z += v2.z; acc0.w += v2.w;
        acc1.x += v3.x; acc1.y += v3.y; acc1.z += v3.z; acc1.w += v3.w;
    }
    if (a + 2 <= cnt) {
        float4 v0 = __ldcs(p);
        float4 v1 = __ldcs(p + 32);
        p += 64;
        a += 2;
        acc0.x += v0.x; acc0.y += v0.y; acc0.z += v0.z; acc0.w += v0.w;
        acc1.x += v1.x; acc1.y += v1.y; acc1.z += v1.z; acc1.w += v1.w;
    }
    if (a < cnt) {
        float4 v0 = __ldcs(p);
        acc0.x += v0.x; acc0.y += v0.y; acc0.z += v0.z; acc0.w += v0.w;
    }

    const float inv = (cnt > 0) ? (1.0f / (float)cnt) : 0.0f;
    float4 rw;
    rw.x = (acc0.x + acc1.x) * inv;
    rw.y = (acc0.y + acc1.y) * inv;
    rw.z = (acc0.z + acc1.z) * inv;
    rw.w = (acc0.w + acc1.w) * inv;

    __stcs((float4*)(out + (size_t)r * FEAT_DIM) + lane, rw);
}

extern "C" void kernel_launch(void* const* d_in, const int* in_sizes, int n_in,
                              void* d_out, int out_size) {
    const float* feat = (const float*)d_in[0];
    const void* idx   = (const void*)d_in[1];
    int n_atoms       = in_sizes[1];

    // One warp per residue; 2 warps per 64-thread block (best tail-skew config).
    int res_per_block = 2;
    int blocks = (NUM_RESIDUES + res_per_block - 1) / res_per_block;
    fused_pool_kernel<<<blocks, 64>>>(feat, idx, n_atoms, (float*)d_out);
}

// round 9
// speedup vs baseline: 1.0214x; 1.0214x over previous
#include <cuda_runtime.h>
#include <cuda_bf16.h>
#include <cstdint>

// ResiduePooling: scatter_mean(atom_features[2e6,128], residue_index(sorted) -> [250000,128])
//
// Two-pass (measured optimum structure):
// Pass 1: offsets from sorted index, one index per thread; predecessor
//         obtained via __shfl_up (lane 0 loads one scalar) -> index read once.
// Pass 2: one warp per residue, 64-thread blocks. Lane owns one float4 of the
//         128-wide row; 512B coalesced LDG.128 streams (evict-streaming),
//         scale by 1/count, one 512B row store. Empty residues write 0.

#define NUM_RESIDUES 250000
#define FEAT_DIM 128

__device__ int g_seg_start[NUM_RESIDUES + 1];

__device__ __forceinline__ bool detect_is64(const int* __restrict__ v, int n) {
    // int64 little-endian values < 2^31: every odd int32 slot is zero.
    int p0 = __ldg(v + 1);
    int p1 = __ldg(v + ((n > 1002) ? 1001 : 1));
    int p2 = __ldg(v + ((n > 100002) ? 100001 : 1));
    int p3 = __ldg(v + (n - 1));
    return ((p0 | p1 | p2 | p3) == 0);
}

__global__ void __launch_bounds__(256) build_offsets_kernel(const void* __restrict__ idxv, int n) {
    const bool is64 = detect_is64((const int*)idxv, n);
    const long long* __restrict__ p64 = (const long long*)idxv;
    const int* __restrict__       p32 = (const int*)idxv;

    const int i    = blockIdx.x * blockDim.x + threadIdx.x;
    const int lane = threadIdx.x & 31;
    const bool valid = (i < n);

    // Coalesced: each thread loads only its own index.
    int r = valid ? (is64 ? (int)p64[i] : p32[i]) : 0;

    // Predecessor via shuffle; lane 0 loads the single straggler.
    int prev = __shfl_up_sync(0xffffffffu, r, 1);
    if (lane == 0)
        prev = (i == 0) ? -1
                        : (is64 ? (int)p64[i - 1] : p32[i - 1]);

    if (!valid) return;

    // This thread owns residue boundaries in (prev, r].
    for (int q = prev + 1; q <= r; q++) g_seg_start[q] = i;

    if (i == n - 1) {
        for (int q = r + 1; q <= NUM_RESIDUES; q++) g_seg_start[q] = n;
    }
}

__global__ void __launch_bounds__(64) pool_kernel(const float* __restrict__ feat,
                                                  float* __restrict__ out) {
    int gwarp = (blockIdx.x * blockDim.x + threadIdx.x) >> 5;  // residue id
    int lane  = threadIdx.x & 31;
    if (gwarp >= NUM_RESIDUES) return;

    int s = __ldg(&g_seg_start[gwarp]);
    int e = __ldg(&g_seg_start[gwarp + 1]);
    int cnt = e - s;

    // Per-row stride in float4 units = 128/4 = 32.
    const float4* __restrict__ p = (const float4*)(feat + (size_t)s * FEAT_DIM) + lane;

    float4 acc0 = make_float4(0.f, 0.f, 0.f, 0.f);
    float4 acc1 = make_float4(0.f, 0.f, 0.f, 0.f);

    int a = 0;
    // Unroll by 4: four independent 512B row reads in flight per warp.
    for (; a + 4 <= cnt; a += 4) {
        float4 v0 = __ldcs(p);
        float4 v1 = __ldcs(p + 32);
        float4 v2 = __ldcs(p + 64);
        float4 v3 = __ldcs(p + 96);
        p += 128;
        acc0.x += v0.x; acc0.y += v0.y; acc0.z += v0.z; acc0.w += v0.w;
        acc1.x += v1.x; acc1.y += v1.y; acc1.z += v1.z; acc1.w += v1.w;
        acc0.x += v2.x; acc0.y += v2.y; acc0.z += v2.z; acc0.w += v2.w;
        acc1.x += v3.x; acc1.y += v3.y; acc1.z += v3.z; acc1.w += v3.w;
    }
    if (a + 2 <= cnt) {
        float4 v0 = __ldcs(p);
        float4 v1 = __ldcs(p + 32);
        p += 64;
        a += 2;
        acc0.x += v0.x; acc0.y += v0.y; acc0.z += v0.z; acc0.w += v0.w;
        acc1.x += v1.x; acc1.y += v1.y; acc1.z += v1.z; acc1.w += v1.w;
    }
    if (a < cnt) {
        float4 v0 = __ldcs(p);
        acc0.x += v0.x; acc0.y += v0.y; acc0.z += v0.z; acc0.w += v0.w;
    }

    float inv = (cnt > 0) ? (1.0f / (float)cnt) : 0.0f;
    float4 r;
    r.x = (acc0.x + acc1.x) * inv;
    r.y = (acc0.y + acc1.y) * inv;
    r.z = (acc0.z + acc1.z) * inv;
    r.w = (acc0.w + acc1.w) * inv;

    __stcs((float4*)(out + (size_t)gwarp * FEAT_DIM) + lane, r);
}

extern "C" void kernel_launch(void* const* d_in, const int* in_sizes, int n_in,
                              void* d_out, int out_size) {
    const float* feat = (const float*)d_in[0];
    const void* idx   = (const void*)d_in[1];
    int n_atoms       = in_sizes[1];

    int threads = 256;
    int blocks = (n_atoms + threads - 1) / threads;
    build_offsets_kernel<<<blocks, threads>>>(idx, n_atoms);

    // 2 warps per block -> 2 residues per block (minimize tail skew)
    int res_per_block = 2;
    int pool_blocks = (NUM_RESIDUES + res_per_block - 1) / res_per_block;
    pool_kernel<<<pool_blocks, 64>>>(feat, (float*)d_out);
}